// round 12
// baseline (speedup 1.0000x reference)
#include <cuda_runtime.h>
#include <cuda_bf16.h>
#include <cstdint>

#define THREADS 256
#define TILE    64

// bf16 tiles, row stride in BYTES (stride/16 odd -> 8-row LDSM phase conflict-free)
#define ASTR1 464   // A1: 64 x [xhi(112) | xlo(112)]
#define BSTR1 464   // B1: 88 x [whi(112) | wlo(112)] (rows 80..87 zero pad)
#define ASTR2 336   // A2: 64 x [hhi(80)  | hlo(80)]
#define BSTR2 336   // B2: 64 x [whi(80)  | wlo(80)]

#define OFF_A1  0         // 64*464 = 29696
#define OFF_A2  29696     // 64*336 = 21504 -> 51200
#define OFF_B1  51200     // 88*464 = 40832 -> 92032
#define OFF_B2  92032     // 64*336 = 21504 -> 113536
#define OFF_B1S 113536    // 96 f32 (80 real + zero pad)
#define OFF_B2S 113920    // 64 f32
#define SMEM_TOTAL 114176 // x2 CTAs = 228352 <= 233472 (228KB/SM)

__device__ __forceinline__ uint32_t smem_u32(const void* p) {
    uint32_t a;
    asm("{ .reg .u64 t; cvta.to.shared.u64 t, %1; cvt.u32.u64 %0, t; }" : "=r"(a) : "l"(p));
    return a;
}

__device__ __forceinline__ void split_pack(float x0, float x1, uint32_t& hi, uint32_t& lo) {
    uint16_t h0 = __bfloat16_as_ushort(__float2bfloat16_rn(x0));
    uint16_t h1 = __bfloat16_as_ushort(__float2bfloat16_rn(x1));
    float f0 = __uint_as_float((uint32_t)h0 << 16);
    float f1 = __uint_as_float((uint32_t)h1 << 16);
    uint16_t l0 = __bfloat16_as_ushort(__float2bfloat16_rn(x0 - f0));
    uint16_t l1 = __bfloat16_as_ushort(__float2bfloat16_rn(x1 - f1));
    hi = (uint32_t)h0 | ((uint32_t)h1 << 16);
    lo = (uint32_t)l0 | ((uint32_t)l1 << 16);
}

__device__ __forceinline__ float fast_tanh(float x) {
    float e = __expf(2.0f * x);
    return 1.0f - __fdividef(2.0f, e + 1.0f);
}

__device__ __forceinline__ void ldsm_x4(uint32_t& r0, uint32_t& r1, uint32_t& r2, uint32_t& r3,
                                        uint32_t addr) {
    asm volatile("ldmatrix.sync.aligned.m8n8.x4.shared.b16 {%0,%1,%2,%3}, [%4];"
        : "=r"(r0), "=r"(r1), "=r"(r2), "=r"(r3) : "r"(addr));
}
__device__ __forceinline__ void ldsm_x2(uint32_t& r0, uint32_t& r1, uint32_t addr) {
    asm volatile("ldmatrix.sync.aligned.m8n8.x2.shared.b16 {%0,%1}, [%2];"
        : "=r"(r0), "=r"(r1) : "r"(addr));
}

__device__ __forceinline__ void mma16816(float* d, uint32_t a0, uint32_t a1, uint32_t a2,
                                         uint32_t a3, uint32_t b0, uint32_t b1) {
    asm volatile(
        "mma.sync.aligned.m16n8k16.row.col.f32.bf16.bf16.f32 "
        "{%0,%1,%2,%3}, {%4,%5,%6,%7}, {%8,%9}, {%0,%1,%2,%3};"
        : "+f"(d[0]), "+f"(d[1]), "+f"(d[2]), "+f"(d[3])
        : "r"(a0), "r"(a1), "r"(a2), "r"(a3), "r"(b0), "r"(b1));
}

extern __shared__ char smem[];

__global__ void __launch_bounds__(THREADS, 2)
edge_mlp_mma(const float* __restrict__ dstf, const float* __restrict__ dsth,
             const float* __restrict__ srcf, const float* __restrict__ srch,
             const float* __restrict__ ef,
             const float* __restrict__ W1, const float* __restrict__ b1,
             const float* __restrict__ W2, const float* __restrict__ b2,
             float* __restrict__ out, int E)
{
    const uint32_t sb = smem_u32(smem);
    const int tid  = threadIdx.x;
    const int lane = tid & 31;
    const int warp = tid >> 5;            // 0..7
    float* b1s = (float*)(smem + OFF_B1S);
    float* b2s = (float*)(smem + OFF_B2S);

    // ---- one-time zero (covers all k-pads, B1 pad rows, b1s pad) ----
    for (int i = tid; i < SMEM_TOTAL / 4; i += THREADS) ((uint32_t*)smem)[i] = 0u;
    __syncthreads();

    // ---- stage split weights (per CTA) ----
    for (int i = tid; i < 80 * 56; i += THREADS) {
        int n = i / 56, c2 = (i - n * 56) * 2;
        float w0 = (c2     < 97) ? W1[n * 97 + c2]     : 0.0f;
        float w1 = (c2 + 1 < 97) ? W1[n * 97 + c2 + 1] : 0.0f;
        uint32_t hi, lo; split_pack(w0, w1, hi, lo);
        *(uint32_t*)(smem + OFF_B1 + n * BSTR1 + c2 * 2)         = hi;
        *(uint32_t*)(smem + OFF_B1 + n * BSTR1 + (112 + c2) * 2) = lo;
    }
    for (int i = tid; i < 64 * 40; i += THREADS) {
        int n = i / 40, c2 = (i - n * 40) * 2;
        float w0 = W2[n * 80 + c2], w1 = W2[n * 80 + c2 + 1];
        uint32_t hi, lo; split_pack(w0, w1, hi, lo);
        *(uint32_t*)(smem + OFF_B2 + n * BSTR2 + c2 * 2)        = hi;
        *(uint32_t*)(smem + OFF_B2 + n * BSTR2 + (80 + c2) * 2) = lo;
    }
    if (tid < 80) b1s[tid] = b1[tid];
    if (tid < 64) b2s[tid] = b2[tid];
    __syncthreads();

    // warp grid: 2 row-groups (m32) x 4 n-groups
    const int mrow  = (warp & 1) * 32;
    const int g     = warp >> 1;          // 0..3
    const int ncolA = g * 24;             // phase A col base (groups 24/24/24/16)
    const int ncolB = g * 16;             // phase B col base
    const int rA = (lane >> 2);
    const int cc = 2 * (lane & 3);

    const int aRow  = lane & 15;
    const int aKof  = (lane >> 4) * 8;
    const int bRow4 = lane & 15;
    const int bKof4 = (lane >> 4) * 8;
    const int bRow2 = lane & 7;
    const int bKof2 = ((lane >> 3) & 1) * 8;

    // staging: 4 threads per row; chunks c = 4q + sub (q=0..5), + c=24 for sub==3
    const int srow = tid >> 2;            // 0..63
    const int sub  = tid & 3;

    const int ntiles = (E + TILE - 1) / TILE;

    // ---- prefetch first tile into registers ----
    float4 px[7];
    {
        int tile0 = blockIdx.x;
        if (tile0 < ntiles) {
            size_t ge = (size_t)(tile0 * TILE + srow);
            bool ok = (int)(ge) < E;
            #pragma unroll
            for (int q = 0; q < 6; q++) {
                int k0 = (4 * q + sub) * 4;
                float4 x = make_float4(0.f, 0.f, 0.f, 0.f);
                if (ok) {
                    if      (k0 < 16) x = *(const float4*)(dstf + ge * 16 + k0);
                    else if (k0 < 48) x = *(const float4*)(dsth + ge * 32 + (k0 - 16));
                    else if (k0 < 64) x = *(const float4*)(srcf + ge * 16 + (k0 - 48));
                    else              x = *(const float4*)(srch + ge * 32 + (k0 - 64));
                }
                px[q] = x;
            }
            px[6] = make_float4((sub == 3 && ok) ? ef[ge] : 0.0f, 0.f, 0.f, 0.f);
        }
    }

    for (int tile = blockIdx.x; tile < ntiles; tile += gridDim.x) {
        const int e0 = tile * TILE;

        // ---- STS prefetched tile -> A1 (split hi/lo) ----
        {
            char* rp = smem + OFF_A1 + srow * ASTR1;
            #pragma unroll
            for (int q = 0; q < 6; q++) {
                int k0 = (4 * q + sub) * 4;
                uint32_t h0, l0, h1, l1;
                split_pack(px[q].x, px[q].y, h0, l0);
                split_pack(px[q].z, px[q].w, h1, l1);
                *(uint32_t*)(rp + k0 * 2)             = h0;
                *(uint32_t*)(rp + k0 * 2 + 4)         = h1;
                *(uint32_t*)(rp + (112 + k0) * 2)     = l0;
                *(uint32_t*)(rp + (112 + k0) * 2 + 4) = l1;
            }
            if (sub == 3) {
                uint32_t h0, l0, h1, l1;
                split_pack(px[6].x, px[6].y, h0, l0);
                split_pack(px[6].z, px[6].w, h1, l1);
                *(uint32_t*)(rp + 96 * 2)             = h0;
                *(uint32_t*)(rp + 96 * 2 + 4)         = h1;
                *(uint32_t*)(rp + (112 + 96) * 2)     = l0;
                *(uint32_t*)(rp + (112 + 96) * 2 + 4) = l1;
            }
        }
        __syncthreads();   // bar1: A1 visible; gates mmaA

        // ---- prefetch NEXT tile ----
        {
            int nt = tile + gridDim.x;
            if (nt < ntiles) {
                size_t ge = (size_t)(nt * TILE + srow);
                bool ok = (int)(ge) < E;
                #pragma unroll
                for (int q = 0; q < 6; q++) {
                    int k0 = (4 * q + sub) * 4;
                    float4 x = make_float4(0.f, 0.f, 0.f, 0.f);
                    if (ok) {
                        if      (k0 < 16) x = *(const float4*)(dstf + ge * 16 + k0);
                        else if (k0 < 48) x = *(const float4*)(dsth + ge * 32 + (k0 - 16));
                        else if (k0 < 64) x = *(const float4*)(srcf + ge * 16 + (k0 - 48));
                        else              x = *(const float4*)(srch + ge * 32 + (k0 - 64));
                    }
                    px[q] = x;
                }
                px[6] = make_float4((sub == 3 && ok) ? ef[ge] : 0.0f, 0.f, 0.f, 0.f);
            }
        }

        // ---- phase A: H[64x80], warp m32 x n24 (g<3) / n16 (g=3), 21 k-steps ----
        float acc[2][3][4];
        #pragma unroll
        for (int h = 0; h < 2; h++)
            #pragma unroll
            for (int j = 0; j < 3; j++)
                #pragma unroll
                for (int q = 0; q < 4; q++) acc[h][j][q] = 0.0f;

        {
            const uint32_t aBase0 = sb + OFF_A1 + (mrow + aRow) * ASTR1 + aKof * 2;
            const uint32_t aBase1 = aBase0 + 16 * ASTR1;
            const uint32_t bBase0 = sb + OFF_B1 + (ncolA + bRow4)      * BSTR1 + bKof4 * 2;
            const uint32_t bBase1 = sb + OFF_B1 + (ncolA + 16 + bRow2) * BSTR1 + bKof2 * 2;

            if (g < 3) {
                #pragma unroll
                for (int s = 0; s < 21; s++) {
                    const int t  = (s < 7) ? 0 : ((s < 14) ? 1 : 2);
                    const int sk = s - ((t == 1) ? 7 : ((t == 2) ? 14 : 0));
                    const int kA = (((t == 1) ? 112 : 0) + sk * 16) * 2;
                    const int kB = (((t == 2) ? 112 : 0) + sk * 16) * 2;
                    uint32_t a0, a1, a2, a3, c0, c1, c2, c3, q0, q1, q2, q3;
                    ldsm_x4(a0, a1, a2, a3, aBase0 + kA);
                    ldsm_x4(c0, c1, c2, c3, aBase1 + kA);
                    ldsm_x4(q0, q1, q2, q3, bBase0 + kB);
                    mma16816(acc[0][0], a0, a1, a2, a3, q0, q2);
                    mma16816(acc[1][0], c0, c1, c2, c3, q0, q2);
                    mma16816(acc[0][1], a0, a1, a2, a3, q1, q3);
                    mma16816(acc[1][1], c0, c1, c2, c3, q1, q3);
                    ldsm_x2(q0, q1, bBase1 + kB);
                    mma16816(acc[0][2], a0, a1, a2, a3, q0, q1);
                    mma16816(acc[1][2], c0, c1, c2, c3, q0, q1);
                }
            } else {
                #pragma unroll
                for (int s = 0; s < 21; s++) {
                    const int t  = (s < 7) ? 0 : ((s < 14) ? 1 : 2);
                    const int sk = s - ((t == 1) ? 7 : ((t == 2) ? 14 : 0));
                    const int kA = (((t == 1) ? 112 : 0) + sk * 16) * 2;
                    const int kB = (((t == 2) ? 112 : 0) + sk * 16) * 2;
                    uint32_t a0, a1, a2, a3, c0, c1, c2, c3, q0, q1, q2, q3;
                    ldsm_x4(a0, a1, a2, a3, aBase0 + kA);
                    ldsm_x4(c0, c1, c2, c3, aBase1 + kA);
                    ldsm_x4(q0, q1, q2, q3, bBase0 + kB);
                    mma16816(acc[0][0], a0, a1, a2, a3, q0, q2);
                    mma16816(acc[1][0], c0, c1, c2, c3, q0, q2);
                    mma16816(acc[0][1], a0, a1, a2, a3, q1, q3);
                    mma16816(acc[1][1], c0, c1, c2, c3, q1, q3);
                }
            }
        }

        // ---- epilogue A: relu(+b1), split -> A2 (skip pad cols >= 80) ----
        {
            const int jmax = (g < 3) ? 3 : 1;   // g3: only j=0 (cols 72..79) valid
            #pragma unroll
            for (int h = 0; h < 2; h++) {
                for (int j = 0; j < jmax; j++) {
                    const int c0 = ncolA + 8 * j + cc;
                    const float bb0 = b1s[c0], bb1 = b1s[c0 + 1];
                    float h00 = fmaxf(acc[h][j][0] + bb0, 0.0f);
                    float h01 = fmaxf(acc[h][j][1] + bb1, 0.0f);
                    float h10 = fmaxf(acc[h][j][2] + bb0, 0.0f);
                    float h11 = fmaxf(acc[h][j][3] + bb1, 0.0f);
                    uint32_t hi, lo;
                    char* rp0 = smem + OFF_A2 + (mrow + 16 * h + rA) * ASTR2;
                    char* rp1 = rp0 + 8 * ASTR2;
                    split_pack(h00, h01, hi, lo);
                    *(uint32_t*)(rp0 + c0 * 2) = hi;  *(uint32_t*)(rp0 + (80 + c0) * 2) = lo;
                    split_pack(h10, h11, hi, lo);
                    *(uint32_t*)(rp1 + c0 * 2) = hi;  *(uint32_t*)(rp1 + (80 + c0) * 2) = lo;
                }
            }
        }
        __syncthreads();   // bar2: A2 complete; also proves all mmaA A1-reads done

        // ---- phase B: O[64x64], warp m32 x n16, 15 k-steps ----
        float acc2[2][2][4];
        #pragma unroll
        for (int h = 0; h < 2; h++)
            #pragma unroll
            for (int j = 0; j < 2; j++)
                #pragma unroll
                for (int q = 0; q < 4; q++) acc2[h][j][q] = 0.0f;

        {
            const uint32_t aBase0 = sb + OFF_A2 + (mrow + aRow) * ASTR2 + aKof * 2;
            const uint32_t aBase1 = aBase0 + 16 * ASTR2;
            const uint32_t bBase0 = sb + OFF_B2 + (ncolB + bRow4) * BSTR2 + bKof4 * 2;

            #pragma unroll
            for (int s = 0; s < 15; s++) {
                const int t  = (s < 5) ? 0 : ((s < 10) ? 1 : 2);
                const int sk = s - ((t == 1) ? 5 : ((t == 2) ? 10 : 0));
                const int kA = (((t == 1) ? 80 : 0) + sk * 16) * 2;
                const int kB = (((t == 2) ? 80 : 0) + sk * 16) * 2;
                uint32_t a0, a1, a2, a3, c0, c1, c2, c3, q0, q1, q2, q3;
                ldsm_x4(a0, a1, a2, a3, aBase0 + kA);
                ldsm_x4(c0, c1, c2, c3, aBase1 + kA);
                ldsm_x4(q0, q1, q2, q3, bBase0 + kB);
                mma16816(acc2[0][0], a0, a1, a2, a3, q0, q2);
                mma16816(acc2[1][0], c0, c1, c2, c3, q0, q2);
                mma16816(acc2[0][1], a0, a1, a2, a3, q1, q3);
                mma16816(acc2[1][1], c0, c1, c2, c3, q1, q3);
            }
        }

        // ---- epilogue B: tanh(+b2) -> direct STG.64 ----
        #pragma unroll
        for (int h = 0; h < 2; h++) {
            const int gr0 = e0 + mrow + 16 * h + rA;
            const int gr1 = gr0 + 8;
            #pragma unroll
            for (int j = 0; j < 2; j++) {
                const int c0 = ncolB + 8 * j + cc;
                const float bb0 = b2s[c0], bb1 = b2s[c0 + 1];
                if (gr0 < E) {
                    float2 v = make_float2(fast_tanh(acc2[h][j][0] + bb0),
                                           fast_tanh(acc2[h][j][1] + bb1));
                    *(float2*)(out + (size_t)gr0 * 64 + c0) = v;
                }
                if (gr1 < E) {
                    float2 v = make_float2(fast_tanh(acc2[h][j][2] + bb0),
                                           fast_tanh(acc2[h][j][3] + bb1));
                    *(float2*)(out + (size_t)gr1 * 64 + c0) = v;
                }
            }
        }
        // next iteration's STS(t+1) safe: bar2 proved all mmaA(t) A1-reads done.
    }
}

extern "C" void kernel_launch(void* const* d_in, const int* in_sizes, int n_in,
                              void* d_out, int out_size) {
    const float* dstf = (const float*)d_in[0];
    const float* dsth = (const float*)d_in[1];
    const float* srcf = (const float*)d_in[2];
    const float* srch = (const float*)d_in[3];
    const float* ef   = (const float*)d_in[4];
    const float* W1   = (const float*)d_in[5];
    const float* b1   = (const float*)d_in[6];
    const float* W2   = (const float*)d_in[7];
    const float* b2   = (const float*)d_in[8];
    float* out = (float*)d_out;
    const int E = in_sizes[4];
    (void)n_in; (void)out_size;

    cudaFuncSetAttribute(edge_mlp_mma,
                         cudaFuncAttributeMaxDynamicSharedMemorySize, SMEM_TOTAL);
    int sms = 148;
    cudaDeviceGetAttribute(&sms, cudaDevAttrMultiProcessorCount, 0);

    edge_mlp_mma<<<2 * sms, THREADS, SMEM_TOTAL>>>(
        dstf, dsth, srcf, srch, ef, W1, b1, W2, b2, out, E);
}

// round 13
// speedup vs baseline: 1.0961x; 1.0961x over previous
#include <cuda_runtime.h>
#include <cuda_bf16.h>
#include <cstdint>

#define THREADS 256
#define TILE    128

// bf16 tiles, row stride in BYTES (stride/16 odd -> 8-row LDSM phase conflict-free)
#define ASTR1 464   // A1: 128 x [xhi(112) | xlo(112)]
#define BSTR1 464   // B1: 80  x [whi(112) | wlo(112)]
#define ASTR2 336   // A2: 128 x [hhi(80)  | hlo(80)]
#define BSTR2 336   // B2: 64  x [whi(80)  | wlo(80)]

#define OFF_A1  0         // 128*464 = 59392
#define OFF_A2  59392     // 128*336 = 43008 -> 102400
#define OFF_B1  102400    // 80*464  = 37120 -> 139520
#define OFF_B2  139520    // 64*336  = 21504 -> 161024
#define OFF_B1S 161024    // 80 f32
#define OFF_B2S 161344    // 64 f32
#define SMEM_TOTAL 161664

__device__ __forceinline__ uint32_t smem_u32(const void* p) {
    uint32_t a;
    asm("{ .reg .u64 t; cvta.to.shared.u64 t, %1; cvt.u32.u64 %0, t; }" : "=r"(a) : "l"(p));
    return a;
}

__device__ __forceinline__ void split_pack(float x0, float x1, uint32_t& hi, uint32_t& lo) {
    uint16_t h0 = __bfloat16_as_ushort(__float2bfloat16_rn(x0));
    uint16_t h1 = __bfloat16_as_ushort(__float2bfloat16_rn(x1));
    float f0 = __uint_as_float((uint32_t)h0 << 16);
    float f1 = __uint_as_float((uint32_t)h1 << 16);
    uint16_t l0 = __bfloat16_as_ushort(__float2bfloat16_rn(x0 - f0));
    uint16_t l1 = __bfloat16_as_ushort(__float2bfloat16_rn(x1 - f1));
    hi = (uint32_t)h0 | ((uint32_t)h1 << 16);
    lo = (uint32_t)l0 | ((uint32_t)l1 << 16);
}

__device__ __forceinline__ float fast_tanh(float x) {
    float e = __expf(2.0f * x);
    return 1.0f - __fdividef(2.0f, e + 1.0f);
}

__device__ __forceinline__ void ldsm_x4(uint32_t& r0, uint32_t& r1, uint32_t& r2, uint32_t& r3,
                                        uint32_t addr) {
    asm volatile("ldmatrix.sync.aligned.m8n8.x4.shared.b16 {%0,%1,%2,%3}, [%4];"
        : "=r"(r0), "=r"(r1), "=r"(r2), "=r"(r3) : "r"(addr));
}
__device__ __forceinline__ void ldsm_x2(uint32_t& r0, uint32_t& r1, uint32_t addr) {
    asm volatile("ldmatrix.sync.aligned.m8n8.x2.shared.b16 {%0,%1}, [%2];"
        : "=r"(r0), "=r"(r1) : "r"(addr));
}

__device__ __forceinline__ void mma16816(float* d, const uint32_t* a,
                                         uint32_t b0, uint32_t b1) {
    asm volatile(
        "mma.sync.aligned.m16n8k16.row.col.f32.bf16.bf16.f32 "
        "{%0,%1,%2,%3}, {%4,%5,%6,%7}, {%8,%9}, {%0,%1,%2,%3};"
        : "+f"(d[0]), "+f"(d[1]), "+f"(d[2]), "+f"(d[3])
        : "r"(a[0]), "r"(a[1]), "r"(a[2]), "r"(a[3]), "r"(b0), "r"(b1));
}

// k-step -> byte offsets for the 3-term split walk (compile-time under unroll)
__device__ __forceinline__ int kmapA1(int s) {
    int t = (s < 7) ? 0 : ((s < 14) ? 1 : 2);
    int sk = s - ((t == 1) ? 7 : ((t == 2) ? 14 : 0));
    return (((t == 1) ? 112 : 0) + sk * 16) * 2;
}
__device__ __forceinline__ int kmapB1(int s) {
    int t = (s < 7) ? 0 : ((s < 14) ? 1 : 2);
    int sk = s - ((t == 1) ? 7 : ((t == 2) ? 14 : 0));
    return (((t == 2) ? 112 : 0) + sk * 16) * 2;
}
__device__ __forceinline__ int kmapA2(int s) {
    int t = (s < 5) ? 0 : ((s < 10) ? 1 : 2);
    int sk = s - ((t == 1) ? 5 : ((t == 2) ? 10 : 0));
    return (((t == 1) ? 80 : 0) + sk * 16) * 2;
}
__device__ __forceinline__ int kmapB2(int s) {
    int t = (s < 5) ? 0 : ((s < 10) ? 1 : 2);
    int sk = s - ((t == 1) ? 5 : ((t == 2) ? 10 : 0));
    return (((t == 2) ? 80 : 0) + sk * 16) * 2;
}

extern __shared__ char smem[];

__global__ void __launch_bounds__(THREADS, 1)
edge_mlp_mma(const float* __restrict__ dstf, const float* __restrict__ dsth,
             const float* __restrict__ srcf, const float* __restrict__ srch,
             const float* __restrict__ ef,
             const float* __restrict__ W1, const float* __restrict__ b1,
             const float* __restrict__ W2, const float* __restrict__ b2,
             float* __restrict__ out, int E)
{
    const uint32_t sb = smem_u32(smem);
    const int tid  = threadIdx.x;
    const int lane = tid & 31;
    const int warp = tid >> 5;            // 0..7
    float* b1s = (float*)(smem + OFF_B1S);
    float* b2s = (float*)(smem + OFF_B2S);

    // ---- one-time zero (covers all k-pads) ----
    for (int i = tid; i < OFF_B1S / 4; i += THREADS) ((uint32_t*)smem)[i] = 0u;
    __syncthreads();

    // ---- stage split weights ----
    for (int i = tid; i < 80 * 56; i += THREADS) {
        int n = i / 56, c2 = (i - n * 56) * 2;
        float w0 = (c2     < 97) ? W1[n * 97 + c2]     : 0.0f;
        float w1 = (c2 + 1 < 97) ? W1[n * 97 + c2 + 1] : 0.0f;
        uint32_t hi, lo; split_pack(w0, w1, hi, lo);
        *(uint32_t*)(smem + OFF_B1 + n * BSTR1 + c2 * 2)         = hi;
        *(uint32_t*)(smem + OFF_B1 + n * BSTR1 + (112 + c2) * 2) = lo;
    }
    for (int i = tid; i < 64 * 40; i += THREADS) {
        int n = i / 40, c2 = (i - n * 40) * 2;
        float w0 = W2[n * 80 + c2], w1 = W2[n * 80 + c2 + 1];
        uint32_t hi, lo; split_pack(w0, w1, hi, lo);
        *(uint32_t*)(smem + OFF_B2 + n * BSTR2 + c2 * 2)        = hi;
        *(uint32_t*)(smem + OFF_B2 + n * BSTR2 + (80 + c2) * 2) = lo;
    }
    if (tid < 80) b1s[tid] = b1[tid];
    if (tid < 64) b2s[tid] = b2[tid];
    __syncthreads();

    // warp tile: m32 x n40 (phase A) / m32 x n32 (phase B)
    const int mrow  = (warp & 3) * 32;
    const int ncolA = (warp >> 2) * 40;
    const int ncolB = (warp >> 2) * 32;
    const int rA = (lane >> 2);
    const int cc = 2 * (lane & 3);

    const int aRow  = lane & 15;
    const int aKof  = (lane >> 4) * 8;
    const int bRow4 = lane & 15;
    const int bKof4 = (lane >> 4) * 8;
    const int bRow2 = lane & 7;
    const int bKof2 = ((lane >> 3) & 1) * 8;

    // staging: 2 threads per row; sub selects even/odd float4 chunks
    const int srow = tid >> 1;            // 0..127
    const int sub  = tid & 1;

    const int ntiles = (E + TILE - 1) / TILE;

    // ---- prefetch first tile into registers ----
    float4 px[12];
    float  pef;
    {
        int tile0 = blockIdx.x;
        if (tile0 < ntiles) {
            size_t ge = (size_t)(tile0 * TILE + srow);
            bool ok = (int)(ge) < E;
            #pragma unroll
            for (int q = 0; q < 12; q++) {
                int k0 = (2 * q + sub) * 4;
                float4 x = make_float4(0.f, 0.f, 0.f, 0.f);
                if (ok) {
                    if      (k0 < 16) x = *(const float4*)(dstf + ge * 16 + k0);
                    else if (k0 < 48) x = *(const float4*)(dsth + ge * 32 + (k0 - 16));
                    else if (k0 < 64) x = *(const float4*)(srcf + ge * 16 + (k0 - 48));
                    else              x = *(const float4*)(srch + ge * 32 + (k0 - 64));
                }
                px[q] = x;
            }
            pef = (sub == 0 && ok) ? ef[ge] : 0.0f;
        }
    }

    for (int tile = blockIdx.x; tile < ntiles; tile += gridDim.x) {
        const int e0 = tile * TILE;

        // ---- STS prefetched tile -> A1 (split hi/lo) ----
        {
            char* rp = smem + OFF_A1 + srow * ASTR1;
            #pragma unroll
            for (int q = 0; q < 12; q++) {
                int k0 = (2 * q + sub) * 4;
                uint32_t h0, l0, h1, l1;
                split_pack(px[q].x, px[q].y, h0, l0);
                split_pack(px[q].z, px[q].w, h1, l1);
                *(uint32_t*)(rp + k0 * 2)             = h0;
                *(uint32_t*)(rp + k0 * 2 + 4)         = h1;
                *(uint32_t*)(rp + (112 + k0) * 2)     = l0;
                *(uint32_t*)(rp + (112 + k0) * 2 + 4) = l1;
            }
            if (sub == 0) {   // ef at col 96; cols 97..99 stay zero from init
                uint32_t hi, lo; split_pack(pef, 0.0f, hi, lo);
                *(uint32_t*)(rp + 96 * 2)         = hi;
                *(uint32_t*)(rp + (112 + 96) * 2) = lo;
            }
        }
        __syncthreads();   // bar1: A1 visible; gates mmaA

        // ---- prefetch NEXT tile (latency hidden behind mmaA/epiA/mmaB) ----
        {
            int nt = tile + gridDim.x;
            if (nt < ntiles) {
                size_t ge = (size_t)(nt * TILE + srow);
                bool ok = (int)(ge) < E;
                #pragma unroll
                for (int q = 0; q < 12; q++) {
                    int k0 = (2 * q + sub) * 4;
                    float4 x = make_float4(0.f, 0.f, 0.f, 0.f);
                    if (ok) {
                        if      (k0 < 16) x = *(const float4*)(dstf + ge * 16 + k0);
                        else if (k0 < 48) x = *(const float4*)(dsth + ge * 32 + (k0 - 16));
                        else if (k0 < 64) x = *(const float4*)(srcf + ge * 16 + (k0 - 48));
                        else              x = *(const float4*)(srch + ge * 32 + (k0 - 64));
                    }
                    px[q] = x;
                }
                pef = (sub == 0 && ok) ? ef[ge] : 0.0f;
            }
        }

        // ---- phase A: H[128x80], warp m32xn40, 21 k-steps, double-buffered ----
        float acc[2][5][4];
        #pragma unroll
        for (int h = 0; h < 2; h++)
            #pragma unroll
            for (int j = 0; j < 5; j++)
                #pragma unroll
                for (int q = 0; q < 4; q++) acc[h][j][q] = 0.0f;

        {
            const uint32_t aBase0 = sb + OFF_A1 + (mrow + aRow) * ASTR1 + aKof * 2;
            const uint32_t aBase1 = aBase0 + 16 * ASTR1;
            const uint32_t bBase0 = sb + OFF_B1 + (ncolA + bRow4)      * BSTR1 + bKof4 * 2;
            const uint32_t bBase1 = sb + OFF_B1 + (ncolA + 16 + bRow4) * BSTR1 + bKof4 * 2;
            const uint32_t bBase2 = sb + OFF_B1 + (ncolA + 32 + bRow2) * BSTR1 + bKof2 * 2;

            uint32_t af[2][8], bf[2][10];
            ldsm_x4(af[0][0], af[0][1], af[0][2], af[0][3], aBase0 + kmapA1(0));
            ldsm_x4(af[0][4], af[0][5], af[0][6], af[0][7], aBase1 + kmapA1(0));
            ldsm_x4(bf[0][0], bf[0][1], bf[0][2], bf[0][3], bBase0 + kmapB1(0));
            ldsm_x4(bf[0][4], bf[0][5], bf[0][6], bf[0][7], bBase1 + kmapB1(0));
            ldsm_x2(bf[0][8], bf[0][9], bBase2 + kmapB1(0));

            #pragma unroll
            for (int s = 0; s < 21; s++) {
                const int cur = s & 1, nxt = cur ^ 1;
                if (s < 20) {
                    ldsm_x4(af[nxt][0], af[nxt][1], af[nxt][2], af[nxt][3], aBase0 + kmapA1(s + 1));
                    ldsm_x4(af[nxt][4], af[nxt][5], af[nxt][6], af[nxt][7], aBase1 + kmapA1(s + 1));
                    ldsm_x4(bf[nxt][0], bf[nxt][1], bf[nxt][2], bf[nxt][3], bBase0 + kmapB1(s + 1));
                    ldsm_x4(bf[nxt][4], bf[nxt][5], bf[nxt][6], bf[nxt][7], bBase1 + kmapB1(s + 1));
                    ldsm_x2(bf[nxt][8], bf[nxt][9], bBase2 + kmapB1(s + 1));
                }
                mma16816(acc[0][0], af[cur],     bf[cur][0], bf[cur][2]);
                mma16816(acc[1][0], af[cur] + 4, bf[cur][0], bf[cur][2]);
                mma16816(acc[0][1], af[cur],     bf[cur][1], bf[cur][3]);
                mma16816(acc[1][1], af[cur] + 4, bf[cur][1], bf[cur][3]);
                mma16816(acc[0][2], af[cur],     bf[cur][4], bf[cur][6]);
                mma16816(acc[1][2], af[cur] + 4, bf[cur][4], bf[cur][6]);
                mma16816(acc[0][3], af[cur],     bf[cur][5], bf[cur][7]);
                mma16816(acc[1][3], af[cur] + 4, bf[cur][5], bf[cur][7]);
                mma16816(acc[0][4], af[cur],     bf[cur][8], bf[cur][9]);
                mma16816(acc[1][4], af[cur] + 4, bf[cur][8], bf[cur][9]);
            }
        }

        // ---- epilogue A: relu(+b1), split -> A2 ----
        #pragma unroll
        for (int h = 0; h < 2; h++) {
            #pragma unroll
            for (int j = 0; j < 5; j++) {
                const int c0 = ncolA + 8 * j + cc;
                const float bb0 = b1s[c0], bb1 = b1s[c0 + 1];
                float h00 = fmaxf(acc[h][j][0] + bb0, 0.0f);
                float h01 = fmaxf(acc[h][j][1] + bb1, 0.0f);
                float h10 = fmaxf(acc[h][j][2] + bb0, 0.0f);
                float h11 = fmaxf(acc[h][j][3] + bb1, 0.0f);
                uint32_t hi, lo;
                char* rp0 = smem + OFF_A2 + (mrow + 16 * h + rA) * ASTR2;
                char* rp1 = rp0 + 8 * ASTR2;
                split_pack(h00, h01, hi, lo);
                *(uint32_t*)(rp0 + c0 * 2) = hi;  *(uint32_t*)(rp0 + (80 + c0) * 2) = lo;
                split_pack(h10, h11, hi, lo);
                *(uint32_t*)(rp1 + c0 * 2) = hi;  *(uint32_t*)(rp1 + (80 + c0) * 2) = lo;
            }
        }
        __syncthreads();   // bar2: A2 complete; also proves all mmaA A1-reads done

        // ---- phase B: O[128x64], warp m32xn32, 15 k-steps, double-buffered ----
        float acc2[2][4][4];
        #pragma unroll
        for (int h = 0; h < 2; h++)
            #pragma unroll
            for (int j = 0; j < 4; j++)
                #pragma unroll
                for (int q = 0; q < 4; q++) acc2[h][j][q] = 0.0f;

        {
            const uint32_t aBase0 = sb + OFF_A2 + (mrow + aRow) * ASTR2 + aKof * 2;
            const uint32_t aBase1 = aBase0 + 16 * ASTR2;
            const uint32_t bBase0 = sb + OFF_B2 + (ncolB + bRow4)      * BSTR2 + bKof4 * 2;
            const uint32_t bBase1 = sb + OFF_B2 + (ncolB + 16 + bRow4) * BSTR2 + bKof4 * 2;

            uint32_t af[2][8], bf[2][8];
            ldsm_x4(af[0][0], af[0][1], af[0][2], af[0][3], aBase0 + kmapA2(0));
            ldsm_x4(af[0][4], af[0][5], af[0][6], af[0][7], aBase1 + kmapA2(0));
            ldsm_x4(bf[0][0], bf[0][1], bf[0][2], bf[0][3], bBase0 + kmapB2(0));
            ldsm_x4(bf[0][4], bf[0][5], bf[0][6], bf[0][7], bBase1 + kmapB2(0));

            #pragma unroll
            for (int s = 0; s < 15; s++) {
                const int cur = s & 1, nxt = cur ^ 1;
                if (s < 14) {
                    ldsm_x4(af[nxt][0], af[nxt][1], af[nxt][2], af[nxt][3], aBase0 + kmapA2(s + 1));
                    ldsm_x4(af[nxt][4], af[nxt][5], af[nxt][6], af[nxt][7], aBase1 + kmapA2(s + 1));
                    ldsm_x4(bf[nxt][0], bf[nxt][1], bf[nxt][2], bf[nxt][3], bBase0 + kmapB2(s + 1));
                    ldsm_x4(bf[nxt][4], bf[nxt][5], bf[nxt][6], bf[nxt][7], bBase1 + kmapB2(s + 1));
                }
                mma16816(acc2[0][0], af[cur],     bf[cur][0], bf[cur][2]);
                mma16816(acc2[1][0], af[cur] + 4, bf[cur][0], bf[cur][2]);
                mma16816(acc2[0][1], af[cur],     bf[cur][1], bf[cur][3]);
                mma16816(acc2[1][1], af[cur] + 4, bf[cur][1], bf[cur][3]);
                mma16816(acc2[0][2], af[cur],     bf[cur][4], bf[cur][6]);
                mma16816(acc2[1][2], af[cur] + 4, bf[cur][4], bf[cur][6]);
                mma16816(acc2[0][3], af[cur],     bf[cur][5], bf[cur][7]);
                mma16816(acc2[1][3], af[cur] + 4, bf[cur][5], bf[cur][7]);
            }
        }

        // ---- epilogue B: tanh(+b2) -> direct STG.64 ----
        #pragma unroll
        for (int h = 0; h < 2; h++) {
            const int gr0 = e0 + mrow + 16 * h + rA;
            const int gr1 = gr0 + 8;
            #pragma unroll
            for (int j = 0; j < 4; j++) {
                const int c0 = ncolB + 8 * j + cc;
                const float bb0 = b2s[c0], bb1 = b2s[c0 + 1];
                if (gr0 < E) {
                    float2 v = make_float2(fast_tanh(acc2[h][j][0] + bb0),
                                           fast_tanh(acc2[h][j][1] + bb1));
                    *(float2*)(out + (size_t)gr0 * 64 + c0) = v;
                }
                if (gr1 < E) {
                    float2 v = make_float2(fast_tanh(acc2[h][j][2] + bb0),
                                           fast_tanh(acc2[h][j][3] + bb1));
                    *(float2*)(out + (size_t)gr1 * 64 + c0) = v;
                }
            }
        }
        // next iteration's STS(t+1) safe: bar2 proved all mmaA(t) A1-reads done.
    }
}

extern "C" void kernel_launch(void* const* d_in, const int* in_sizes, int n_in,
                              void* d_out, int out_size) {
    const float* dstf = (const float*)d_in[0];
    const float* dsth = (const float*)d_in[1];
    const float* srcf = (const float*)d_in[2];
    const float* srch = (const float*)d_in[3];
    const float* ef   = (const float*)d_in[4];
    const float* W1   = (const float*)d_in[5];
    const float* b1   = (const float*)d_in[6];
    const float* W2   = (const float*)d_in[7];
    const float* b2   = (const float*)d_in[8];
    float* out = (float*)d_out;
    const int E = in_sizes[4];
    (void)n_in; (void)out_size;

    cudaFuncSetAttribute(edge_mlp_mma,
                         cudaFuncAttributeMaxDynamicSharedMemorySize, SMEM_TOTAL);
    int sms = 148;
    cudaDeviceGetAttribute(&sms, cudaDevAttrMultiProcessorCount, 0);

    edge_mlp_mma<<<sms, THREADS, SMEM_TOTAL>>>(
        dstf, dsth, srcf, srch, ef, W1, b1, W2, b2, out, E);
}

// round 14
// speedup vs baseline: 1.4670x; 1.3385x over previous
#include <cuda_runtime.h>
#include <cstdint>

#define THREADS 256
#define TILE    128

// fp32/tf32 tiles. Word strides chosen so (row*stride + col) mod 32 is a perfect
// permutation over 8 rows x 4 cols (stride % 8 == 4) -> conflict-free LDS.32 frags.
#define AW1 108   // A1/W1 row stride in words (cols 0..96 data, 97..107 zero)
#define AW2 84    // A2/W2 row stride in words (cols 0..79)

#define OFF_A1  0         // 128*108*4 = 55296
#define OFF_A2  55296     // 128*84*4  = 43008 -> 98304
#define OFF_B1  98304     // 80*108*4  = 34560 -> 132864
#define OFF_B2  132864    // 64*84*4   = 21504 -> 154368
#define OFF_B1S 154368    // 80 f32
#define OFF_B2S 154688    // 64 f32
#define SMEM_TOTAL 154944

__device__ __forceinline__ uint32_t f2tf(float f) {
    uint32_t r; asm("cvt.rna.tf32.f32 %0, %1;" : "=r"(r) : "f"(f)); return r;
}

__device__ __forceinline__ float fast_tanh(float x) {
    float e = __expf(2.0f * x);
    return 1.0f - __fdividef(2.0f, e + 1.0f);
}

__device__ __forceinline__ void mma_tf32(float* d, uint32_t a0, uint32_t a1,
                                         uint32_t a2, uint32_t a3,
                                         uint32_t b0, uint32_t b1) {
    asm volatile(
        "mma.sync.aligned.m16n8k8.row.col.f32.tf32.tf32.f32 "
        "{%0,%1,%2,%3}, {%4,%5,%6,%7}, {%8,%9}, {%0,%1,%2,%3};"
        : "+f"(d[0]), "+f"(d[1]), "+f"(d[2]), "+f"(d[3])
        : "r"(a0), "r"(a1), "r"(a2), "r"(a3), "r"(b0), "r"(b1));
}

extern __shared__ char smem[];

__global__ void __launch_bounds__(THREADS, 1)
edge_mlp_tf32(const float* __restrict__ dstf, const float* __restrict__ dsth,
              const float* __restrict__ srcf, const float* __restrict__ srch,
              const float* __restrict__ ef,
              const float* __restrict__ W1, const float* __restrict__ b1,
              const float* __restrict__ W2, const float* __restrict__ b2,
              float* __restrict__ out, int E)
{
    const int tid  = threadIdx.x;
    const int lane = tid & 31;
    const int warp = tid >> 5;            // 0..7
    float* b1s = (float*)(smem + OFF_B1S);
    float* b2s = (float*)(smem + OFF_B2S);

    uint32_t* A1w = (uint32_t*)(smem + OFF_A1);
    uint32_t* A2w = (uint32_t*)(smem + OFF_A2);
    uint32_t* B1w = (uint32_t*)(smem + OFF_B1);
    uint32_t* B2w = (uint32_t*)(smem + OFF_B2);

    // ---- one-time zero (covers all k-pads) ----
    for (int i = tid; i < OFF_B1S / 4; i += THREADS) ((uint32_t*)smem)[i] = 0u;
    __syncthreads();

    // ---- stage weights as tf32 ----
    for (int i = tid; i < 80 * 97; i += THREADS) {
        int n = i / 97, c = i - n * 97;
        B1w[n * AW1 + c] = f2tf(W1[i]);
    }
    for (int i = tid; i < 64 * 80; i += THREADS) {
        int n = i / 80, c = i - n * 80;
        B2w[n * AW2 + c] = f2tf(W2[i]);
    }
    if (tid < 80) b1s[tid] = b1[tid];
    if (tid < 64) b2s[tid] = b2[tid];
    __syncthreads();

    // warp tile: m32 x n40 (phase A) / m32 x n32 (phase B)
    const int mrow  = (warp & 3) * 32;
    const int ncolA = (warp >> 2) * 40;
    const int ncolB = (warp >> 2) * 32;
    const int rA = (lane >> 2);           // frag row within m16
    const int cc = 2 * (lane & 3);        // acc col pair base within n8
    const int fc = (lane & 3);            // frag k col within k8

    // staging: 2 threads per row; sub selects even/odd float4 chunks
    const int srow = tid >> 1;            // 0..127
    const int sub  = tid & 1;

    const int ntiles = (E + TILE - 1) / TILE;

    // ---- prefetch first tile into registers ----
    float4 px[12];
    float  pef;
    {
        int tile0 = blockIdx.x;
        if (tile0 < ntiles) {
            size_t ge = (size_t)(tile0 * TILE + srow);
            bool ok = (int)(ge) < E;
            #pragma unroll
            for (int q = 0; q < 12; q++) {
                int k0 = (2 * q + sub) * 4;
                float4 x = make_float4(0.f, 0.f, 0.f, 0.f);
                if (ok) {
                    if      (k0 < 16) x = *(const float4*)(dstf + ge * 16 + k0);
                    else if (k0 < 48) x = *(const float4*)(dsth + ge * 32 + (k0 - 16));
                    else if (k0 < 64) x = *(const float4*)(srcf + ge * 16 + (k0 - 48));
                    else              x = *(const float4*)(srch + ge * 32 + (k0 - 64));
                }
                px[q] = x;
            }
            pef = (sub == 0 && ok) ? ef[ge] : 0.0f;
        }
    }

    for (int tile = blockIdx.x; tile < ntiles; tile += gridDim.x) {
        const int e0 = tile * TILE;

        // ---- STS prefetched tile -> A1 as tf32 (contiguous STS.128) ----
        {
            uint32_t* rp = A1w + srow * AW1;
            #pragma unroll
            for (int q = 0; q < 12; q++) {
                int k0 = (2 * q + sub) * 4;
                uint4 t;
                t.x = f2tf(px[q].x); t.y = f2tf(px[q].y);
                t.z = f2tf(px[q].z); t.w = f2tf(px[q].w);
                *(uint4*)(rp + k0) = t;
            }
            if (sub == 0) rp[96] = f2tf(pef);   // cols 97..107 stay zero from init
        }
        __syncthreads();   // bar1: A1 visible; gates mmaA

        // ---- prefetch NEXT tile (latency hidden behind mmaA/epiA/mmaB) ----
        {
            int nt = tile + gridDim.x;
            if (nt < ntiles) {
                size_t ge = (size_t)(nt * TILE + srow);
                bool ok = (int)(ge) < E;
                #pragma unroll
                for (int q = 0; q < 12; q++) {
                    int k0 = (2 * q + sub) * 4;
                    float4 x = make_float4(0.f, 0.f, 0.f, 0.f);
                    if (ok) {
                        if      (k0 < 16) x = *(const float4*)(dstf + ge * 16 + k0);
                        else if (k0 < 48) x = *(const float4*)(dsth + ge * 32 + (k0 - 16));
                        else if (k0 < 64) x = *(const float4*)(srcf + ge * 16 + (k0 - 48));
                        else              x = *(const float4*)(srch + ge * 32 + (k0 - 64));
                    }
                    px[q] = x;
                }
                pef = (sub == 0 && ok) ? ef[ge] : 0.0f;
            }
        }

        // ---- phase A: H[128x80], warp m32 x n40, 13 tf32 k8-steps ----
        float acc[2][5][4];
        #pragma unroll
        for (int h = 0; h < 2; h++)
            #pragma unroll
            for (int j = 0; j < 5; j++)
                #pragma unroll
                for (int q = 0; q < 4; q++) acc[h][j][q] = 0.0f;

        {
            const uint32_t* aR0 = A1w + (mrow + rA) * AW1 + fc;        // rows rA, rA+8
            const uint32_t* aR1 = A1w + (mrow + 16 + rA) * AW1 + fc;   // rows +16, +24
            const uint32_t* bR  = B1w + fc;

            #pragma unroll
            for (int s = 0; s < 13; s++) {
                const int k = s * 8;
                uint32_t a0 = aR0[k],            a1 = aR0[8 * AW1 + k];
                uint32_t a2 = aR0[k + 4],        a3 = aR0[8 * AW1 + k + 4];
                uint32_t c0 = aR1[k],            c1 = aR1[8 * AW1 + k];
                uint32_t c2 = aR1[k + 4],        c3 = aR1[8 * AW1 + k + 4];
                #pragma unroll
                for (int j = 0; j < 5; j++) {
                    const uint32_t* bp = bR + (ncolA + 8 * j + rA) * AW1 + k;
                    uint32_t b0 = bp[0], b1v = bp[4];
                    mma_tf32(acc[0][j], a0, a1, a2, a3, b0, b1v);
                    mma_tf32(acc[1][j], c0, c1, c2, c3, b0, b1v);
                }
            }
        }

        // ---- epilogue A: relu(+b1) -> tf32 -> A2 (STS.64) ----
        #pragma unroll
        for (int h = 0; h < 2; h++) {
            #pragma unroll
            for (int j = 0; j < 5; j++) {
                const int c0 = ncolA + 8 * j + cc;
                const float bb0 = b1s[c0], bb1 = b1s[c0 + 1];
                uint32_t* rp0 = A2w + (mrow + 16 * h + rA) * AW2;
                uint32_t* rp1 = rp0 + 8 * AW2;
                uint2 v0, v1;
                v0.x = f2tf(fmaxf(acc[h][j][0] + bb0, 0.0f));
                v0.y = f2tf(fmaxf(acc[h][j][1] + bb1, 0.0f));
                v1.x = f2tf(fmaxf(acc[h][j][2] + bb0, 0.0f));
                v1.y = f2tf(fmaxf(acc[h][j][3] + bb1, 0.0f));
                *(uint2*)(rp0 + c0) = v0;
                *(uint2*)(rp1 + c0) = v1;
            }
        }
        __syncthreads();   // bar2: A2 complete; also proves all mmaA A1-reads done

        // ---- phase B: O[128x64], warp m32 x n32, 10 tf32 k8-steps ----
        float acc2[2][4][4];
        #pragma unroll
        for (int h = 0; h < 2; h++)
            #pragma unroll
            for (int j = 0; j < 4; j++)
                #pragma unroll
                for (int q = 0; q < 4; q++) acc2[h][j][q] = 0.0f;

        {
            const uint32_t* aR0 = A2w + (mrow + rA) * AW2 + fc;
            const uint32_t* aR1 = A2w + (mrow + 16 + rA) * AW2 + fc;
            const uint32_t* bR  = B2w + fc;

            #pragma unroll
            for (int s = 0; s < 10; s++) {
                const int k = s * 8;
                uint32_t a0 = aR0[k],            a1 = aR0[8 * AW2 + k];
                uint32_t a2 = aR0[k + 4],        a3 = aR0[8 * AW2 + k + 4];
                uint32_t c0 = aR1[k],            c1 = aR1[8 * AW2 + k];
                uint32_t c2 = aR1[k + 4],        c3 = aR1[8 * AW2 + k + 4];
                #pragma unroll
                for (int j = 0; j < 4; j++) {
                    const uint32_t* bp = bR + (ncolB + 8 * j + rA) * AW2 + k;
                    uint32_t b0 = bp[0], b1v = bp[4];
                    mma_tf32(acc2[0][j], a0, a1, a2, a3, b0, b1v);
                    mma_tf32(acc2[1][j], c0, c1, c2, c3, b0, b1v);
                }
            }
        }

        // ---- epilogue B: tanh(+b2) -> direct STG.64 ----
        #pragma unroll
        for (int h = 0; h < 2; h++) {
            const int gr0 = e0 + mrow + 16 * h + rA;
            const int gr1 = gr0 + 8;
            #pragma unroll
            for (int j = 0; j < 4; j++) {
                const int c0 = ncolB + 8 * j + cc;
                const float bb0 = b2s[c0], bb1 = b2s[c0 + 1];
                if (gr0 < E) {
                    float2 v = make_float2(fast_tanh(acc2[h][j][0] + bb0),
                                           fast_tanh(acc2[h][j][1] + bb1));
                    *(float2*)(out + (size_t)gr0 * 64 + c0) = v;
                }
                if (gr1 < E) {
                    float2 v = make_float2(fast_tanh(acc2[h][j][2] + bb0),
                                           fast_tanh(acc2[h][j][3] + bb1));
                    *(float2*)(out + (size_t)gr1 * 64 + c0) = v;
                }
            }
        }
        // next iteration's STS(t+1) safe: bar2 proved all mmaA(t) A1-reads done;
        // mmaB reads only A2/B2, disjoint from A1.
    }
}

extern "C" void kernel_launch(void* const* d_in, const int* in_sizes, int n_in,
                              void* d_out, int out_size) {
    const float* dstf = (const float*)d_in[0];
    const float* dsth = (const float*)d_in[1];
    const float* srcf = (const float*)d_in[2];
    const float* srch = (const float*)d_in[3];
    const float* ef   = (const float*)d_in[4];
    const float* W1   = (const float*)d_in[5];
    const float* b1   = (const float*)d_in[6];
    const float* W2   = (const float*)d_in[7];
    const float* b2   = (const float*)d_in[8];
    float* out = (float*)d_out;
    const int E = in_sizes[4];
    (void)n_in; (void)out_size;

    cudaFuncSetAttribute(edge_mlp_tf32,
                         cudaFuncAttributeMaxDynamicSharedMemorySize, SMEM_TOTAL);
    int sms = 148;
    cudaDeviceGetAttribute(&sms, cudaDevAttrMultiProcessorCount, 0);

    edge_mlp_tf32<<<sms, THREADS, SMEM_TOTAL>>>(
        dstf, dsth, srcf, srch, ef, W1, b1, W2, b2, out, E);
}

// round 15
// speedup vs baseline: 1.4690x; 1.0014x over previous
#include <cuda_runtime.h>
#include <cstdint>

#define THREADS 256
#define TILE    128

// fp32/tf32 tiles. Word strides % 8 == 4 -> conflict-free LDS.32 frag reads.
#define AW1 108   // A1/W1 row stride in words (cols 0..96 data, 97..107 zero)
#define AW2 84    // A2/W2 row stride in words (cols 0..79)

#define OFF_A1  0         // 128*108*4 = 55296
#define OFF_A2  55296     // 128*84*4  = 43008 -> 98304
#define OFF_B1  98304     // 80*108*4  = 34560 -> 132864
#define OFF_B2  132864    // 64*84*4   = 21504 -> 154368
#define OFF_B1S 154368    // 80 f32
#define OFF_B2S 154688    // 64 f32
#define SMEM_TOTAL 154944

// pair barrier: warps {p, p+4} (the two n-groups of row-group p) sync on id p+1
#define PAIR_BAR(p) asm volatile("bar.sync %0, 64;" :: "r"((p) + 1) : "memory")

__device__ __forceinline__ uint32_t f2tf(float f) {
    uint32_t r; asm("cvt.rna.tf32.f32 %0, %1;" : "=r"(r) : "f"(f)); return r;
}

__device__ __forceinline__ float fast_tanh(float x) {
    float e = __expf(2.0f * x);
    return 1.0f - __fdividef(2.0f, e + 1.0f);
}

__device__ __forceinline__ void mma_tf32(float* d, uint32_t a0, uint32_t a1,
                                         uint32_t a2, uint32_t a3,
                                         uint32_t b0, uint32_t b1) {
    asm volatile(
        "mma.sync.aligned.m16n8k8.row.col.f32.tf32.tf32.f32 "
        "{%0,%1,%2,%3}, {%4,%5,%6,%7}, {%8,%9}, {%0,%1,%2,%3};"
        : "+f"(d[0]), "+f"(d[1]), "+f"(d[2]), "+f"(d[3])
        : "r"(a0), "r"(a1), "r"(a2), "r"(a3), "r"(b0), "r"(b1));
}

extern __shared__ char smem[];

__global__ void __launch_bounds__(THREADS, 1)
edge_mlp_tf32(const float* __restrict__ dstf, const float* __restrict__ dsth,
              const float* __restrict__ srcf, const float* __restrict__ srch,
              const float* __restrict__ ef,
              const float* __restrict__ W1, const float* __restrict__ b1,
              const float* __restrict__ W2, const float* __restrict__ b2,
              float* __restrict__ out, int E)
{
    const int tid  = threadIdx.x;
    const int lane = tid & 31;
    const int warp = tid >> 5;            // 0..7
    const int pg   = warp & 3;            // row-group / pair id (= SMSP)
    float* b1s = (float*)(smem + OFF_B1S);
    float* b2s = (float*)(smem + OFF_B2S);

    uint32_t* A1w = (uint32_t*)(smem + OFF_A1);
    uint32_t* A2w = (uint32_t*)(smem + OFF_A2);
    uint32_t* B1w = (uint32_t*)(smem + OFF_B1);
    uint32_t* B2w = (uint32_t*)(smem + OFF_B2);

    // ---- one-time zero (covers all k-pads) ----
    for (int i = tid; i < OFF_B1S / 4; i += THREADS) ((uint32_t*)smem)[i] = 0u;
    __syncthreads();

    // ---- stage weights as tf32 ----
    for (int i = tid; i < 80 * 97; i += THREADS) {
        int n = i / 97, c = i - n * 97;
        B1w[n * AW1 + c] = f2tf(W1[i]);
    }
    for (int i = tid; i < 64 * 80; i += THREADS) {
        int n = i / 80, c = i - n * 80;
        B2w[n * AW2 + c] = f2tf(W2[i]);
    }
    if (tid < 80) b1s[tid] = b1[tid];
    if (tid < 64) b2s[tid] = b2[tid];
    __syncthreads();

    // warp tile: m32 x n40 (phase A) / m32 x n32 (phase B)
    const int mrow  = pg * 32;
    const int ncolA = (warp >> 2) * 40;
    const int ncolB = (warp >> 2) * 32;
    const int rA = (lane >> 2);           // frag row within m16
    const int cc = 2 * (lane & 3);        // acc col pair base within n8
    const int fc = (lane & 3);            // frag k col within k8

    // staging: pair p stages ONLY its own rows mrow..mrow+31.
    // pairtid 0..63 over warps {p, p+4}; 2 threads per row.
    const int pairtid = ((warp >> 2) << 5) | lane;
    const int srow = mrow + (pairtid >> 1);
    const int sub  = pairtid & 1;

    const int ntiles = (E + TILE - 1) / TILE;

    // ---- prefetch first tile into registers ----
    float4 px[12];
    float  pef;
    {
        int tile0 = blockIdx.x;
        if (tile0 < ntiles) {
            size_t ge = (size_t)(tile0 * TILE + srow);
            bool ok = (int)(ge) < E;
            #pragma unroll
            for (int q = 0; q < 12; q++) {
                int k0 = (2 * q + sub) * 4;
                float4 x = make_float4(0.f, 0.f, 0.f, 0.f);
                if (ok) {
                    if      (k0 < 16) x = *(const float4*)(dstf + ge * 16 + k0);
                    else if (k0 < 48) x = *(const float4*)(dsth + ge * 32 + (k0 - 16));
                    else if (k0 < 64) x = *(const float4*)(srcf + ge * 16 + (k0 - 48));
                    else              x = *(const float4*)(srch + ge * 32 + (k0 - 64));
                }
                px[q] = x;
            }
            pef = (sub == 0 && ok) ? ef[ge] : 0.0f;
        }
    }

    for (int tile = blockIdx.x; tile < ntiles; tile += gridDim.x) {
        const int e0 = tile * TILE;

        // ---- STS prefetched rows -> A1 as tf32 (pair-local rows only) ----
        {
            uint32_t* rp = A1w + srow * AW1;
            #pragma unroll
            for (int q = 0; q < 12; q++) {
                int k0 = (2 * q + sub) * 4;
                uint4 t;
                t.x = f2tf(px[q].x); t.y = f2tf(px[q].y);
                t.z = f2tf(px[q].z); t.w = f2tf(px[q].w);
                *(uint4*)(rp + k0) = t;
            }
            if (sub == 0) rp[96] = f2tf(pef);   // cols 97..107 stay zero from init
        }
        PAIR_BAR(pg);   // bar1: pair's A1 rows visible; gates pair's mmaA

        // ---- prefetch NEXT tile (latency hidden behind mmaA/epiA/mmaB) ----
        {
            int nt = tile + gridDim.x;
            if (nt < ntiles) {
                size_t ge = (size_t)(nt * TILE + srow);
                bool ok = (int)(ge) < E;
                #pragma unroll
                for (int q = 0; q < 12; q++) {
                    int k0 = (2 * q + sub) * 4;
                    float4 x = make_float4(0.f, 0.f, 0.f, 0.f);
                    if (ok) {
                        if      (k0 < 16) x = *(const float4*)(dstf + ge * 16 + k0);
                        else if (k0 < 48) x = *(const float4*)(dsth + ge * 32 + (k0 - 16));
                        else if (k0 < 64) x = *(const float4*)(srcf + ge * 16 + (k0 - 48));
                        else              x = *(const float4*)(srch + ge * 32 + (k0 - 64));
                    }
                    px[q] = x;
                }
                pef = (sub == 0 && ok) ? ef[ge] : 0.0f;
            }
        }

        // ---- phase A: H rows mrow..mrow+31, warp m32 x n40, 13 tf32 k8-steps ----
        float acc[2][5][4];
        #pragma unroll
        for (int h = 0; h < 2; h++)
            #pragma unroll
            for (int j = 0; j < 5; j++)
                #pragma unroll
                for (int q = 0; q < 4; q++) acc[h][j][q] = 0.0f;

        {
            const uint32_t* aR0 = A1w + (mrow + rA) * AW1 + fc;        // rows rA, rA+8
            const uint32_t* aR1 = A1w + (mrow + 16 + rA) * AW1 + fc;   // rows +16, +24
            const uint32_t* bR  = B1w + fc;

            #pragma unroll
            for (int s = 0; s < 13; s++) {
                const int k = s * 8;
                uint32_t a0 = aR0[k],            a1 = aR0[8 * AW1 + k];
                uint32_t a2 = aR0[k + 4],        a3 = aR0[8 * AW1 + k + 4];
                uint32_t c0 = aR1[k],            c1 = aR1[8 * AW1 + k];
                uint32_t c2 = aR1[k + 4],        c3 = aR1[8 * AW1 + k + 4];
                #pragma unroll
                for (int j = 0; j < 5; j++) {
                    const uint32_t* bp = bR + (ncolA + 8 * j + rA) * AW1 + k;
                    uint32_t b0 = bp[0], b1v = bp[4];
                    mma_tf32(acc[0][j], a0, a1, a2, a3, b0, b1v);
                    mma_tf32(acc[1][j], c0, c1, c2, c3, b0, b1v);
                }
            }
        }

        // ---- epilogue A: relu(+b1) -> tf32 -> A2 (pair-local rows) ----
        #pragma unroll
        for (int h = 0; h < 2; h++) {
            #pragma unroll
            for (int j = 0; j < 5; j++) {
                const int c0 = ncolA + 8 * j + cc;
                const float bb0 = b1s[c0], bb1 = b1s[c0 + 1];
                uint32_t* rp0 = A2w + (mrow + 16 * h + rA) * AW2;
                uint32_t* rp1 = rp0 + 8 * AW2;
                uint2 v0, v1;
                v0.x = f2tf(fmaxf(acc[h][j][0] + bb0, 0.0f));
                v0.y = f2tf(fmaxf(acc[h][j][1] + bb1, 0.0f));
                v1.x = f2tf(fmaxf(acc[h][j][2] + bb0, 0.0f));
                v1.y = f2tf(fmaxf(acc[h][j][3] + bb1, 0.0f));
                *(uint2*)(rp0 + c0) = v0;
                *(uint2*)(rp1 + c0) = v1;
            }
        }
        PAIR_BAR(pg);   // bar2: pair's A2 rows complete; proves pair's mmaA A1-reads done

        // ---- phase B: O rows mrow..mrow+31, warp m32 x n32, 10 tf32 k8-steps ----
        float acc2[2][4][4];
        #pragma unroll
        for (int h = 0; h < 2; h++)
            #pragma unroll
            for (int j = 0; j < 4; j++)
                #pragma unroll
                for (int q = 0; q < 4; q++) acc2[h][j][q] = 0.0f;

        {
            const uint32_t* aR0 = A2w + (mrow + rA) * AW2 + fc;
            const uint32_t* aR1 = A2w + (mrow + 16 + rA) * AW2 + fc;
            const uint32_t* bR  = B2w + fc;

            #pragma unroll
            for (int s = 0; s < 10; s++) {
                const int k = s * 8;
                uint32_t a0 = aR0[k],            a1 = aR0[8 * AW2 + k];
                uint32_t a2 = aR0[k + 4],        a3 = aR0[8 * AW2 + k + 4];
                uint32_t c0 = aR1[k],            c1 = aR1[8 * AW2 + k];
                uint32_t c2 = aR1[k + 4],        c3 = aR1[8 * AW2 + k + 4];
                #pragma unroll
                for (int j = 0; j < 4; j++) {
                    const uint32_t* bp = bR + (ncolB + 8 * j + rA) * AW2 + k;
                    uint32_t b0 = bp[0], b1v = bp[4];
                    mma_tf32(acc2[0][j], a0, a1, a2, a3, b0, b1v);
                    mma_tf32(acc2[1][j], c0, c1, c2, c3, b0, b1v);
                }
            }
        }

        // ---- epilogue B: tanh(+b2) -> direct STG.64 ----
        #pragma unroll
        for (int h = 0; h < 2; h++) {
            const int gr0 = e0 + mrow + 16 * h + rA;
            const int gr1 = gr0 + 8;
            #pragma unroll
            for (int j = 0; j < 4; j++) {
                const int c0 = ncolB + 8 * j + cc;
                const float bb0 = b2s[c0], bb1 = b2s[c0 + 1];
                if (gr0 < E) {
                    float2 v = make_float2(fast_tanh(acc2[h][j][0] + bb0),
                                           fast_tanh(acc2[h][j][1] + bb1));
                    *(float2*)(out + (size_t)gr0 * 64 + c0) = v;
                }
                if (gr1 < E) {
                    float2 v = make_float2(fast_tanh(acc2[h][j][2] + bb0),
                                           fast_tanh(acc2[h][j][3] + bb1));
                    *(float2*)(out + (size_t)gr1 * 64 + c0) = v;
                }
            }
        }
        // next iteration's STS(t+1) into this pair's A1 rows is safe: pair bar2
        // proved both pair warps finished mmaA(t); mmaB reads only A2/B2. All
        // A1/A2 rows are pair-private; B1/B2 are read-only weights.
    }
}

extern "C" void kernel_launch(void* const* d_in, const int* in_sizes, int n_in,
                              void* d_out, int out_size) {
    const float* dstf = (const float*)d_in[0];
    const float* dsth = (const float*)d_in[1];
    const float* srcf = (const float*)d_in[2];
    const float* srch = (const float*)d_in[3];
    const float* ef   = (const float*)d_in[4];
    const float* W1   = (const float*)d_in[5];
    const float* b1   = (const float*)d_in[6];
    const float* W2   = (const float*)d_in[7];
    const float* b2   = (const float*)d_in[8];
    float* out = (float*)d_out;
    const int E = in_sizes[4];
    (void)n_in; (void)out_size;

    cudaFuncSetAttribute(edge_mlp_tf32,
                         cudaFuncAttributeMaxDynamicSharedMemorySize, SMEM_TOTAL);
    int sms = 148;
    cudaDeviceGetAttribute(&sms, cudaDevAttrMultiProcessorCount, 0);

    edge_mlp_tf32<<<sms, THREADS, SMEM_TOTAL>>>(
        dstf, dsth, srcf, srch, ef, W1, b1, W2, b2, out, E);
}

// round 16
// speedup vs baseline: 1.5100x; 1.0279x over previous
#include <cuda_runtime.h>
#include <cstdint>

#define THREADS 256
#define TILE    128

// fp32/tf32 tiles. Word strides % 8 == 4 -> conflict-free LDS.32 frag reads.
#define AW1 108   // A1/W1 row stride in words (cols 0..96 data, 97..107 zero)
#define AW2 84    // A2/W2 row stride in words (cols 0..79)

#define OFF_A1  0         // 128*108*4 = 55296
#define OFF_A2  55296     // 128*84*4  = 43008 -> 98304
#define OFF_B1  98304     // 80*108*4  = 34560 -> 132864
#define OFF_B2  132864    // 64*84*4   = 21504 -> 154368
#define OFF_B1S 154368    // 80 f32
#define OFF_B2S 154688    // 64 f32
#define SMEM_TOTAL 154944

// pair barrier: warps {2p, 2p+1} (two n-groups of row-group p) sync on id p+1.
// warp->SMSP is warp&3, so pair p spans TWO SMSPs, and each SMSP hosts warps
// of two DIFFERENT pairs -> independent streams per scheduler.
#define PAIR_BAR(p) asm volatile("bar.sync %0, 64;" :: "r"((p) + 1) : "memory")

__device__ __forceinline__ uint32_t f2tf(float f) {
    uint32_t r; asm("cvt.rna.tf32.f32 %0, %1;" : "=r"(r) : "f"(f)); return r;
}

__device__ __forceinline__ float fast_tanh(float x) {
    float e = __expf(2.0f * x);
    return 1.0f - __fdividef(2.0f, e + 1.0f);
}

__device__ __forceinline__ void mma_tf32(float* d, uint32_t a0, uint32_t a1,
                                         uint32_t a2, uint32_t a3,
                                         uint32_t b0, uint32_t b1) {
    asm volatile(
        "mma.sync.aligned.m16n8k8.row.col.f32.tf32.tf32.f32 "
        "{%0,%1,%2,%3}, {%4,%5,%6,%7}, {%8,%9}, {%0,%1,%2,%3};"
        : "+f"(d[0]), "+f"(d[1]), "+f"(d[2]), "+f"(d[3])
        : "r"(a0), "r"(a1), "r"(a2), "r"(a3), "r"(b0), "r"(b1));
}

extern __shared__ char smem[];

__global__ void __launch_bounds__(THREADS, 1)
edge_mlp_tf32(const float* __restrict__ dstf, const float* __restrict__ dsth,
              const float* __restrict__ srcf, const float* __restrict__ srch,
              const float* __restrict__ ef,
              const float* __restrict__ W1, const float* __restrict__ b1,
              const float* __restrict__ W2, const float* __restrict__ b2,
              float* __restrict__ out, int E)
{
    const int tid  = threadIdx.x;
    const int lane = tid & 31;
    const int warp = tid >> 5;            // 0..7
    const int pg   = warp >> 1;           // row-group / pair id (spans 2 SMSPs)
    const int ng   = warp & 1;            // n-group within pair
    float* b1s = (float*)(smem + OFF_B1S);
    float* b2s = (float*)(smem + OFF_B2S);

    uint32_t* A1w = (uint32_t*)(smem + OFF_A1);
    uint32_t* A2w = (uint32_t*)(smem + OFF_A2);
    uint32_t* B1w = (uint32_t*)(smem + OFF_B1);
    uint32_t* B2w = (uint32_t*)(smem + OFF_B2);

    // ---- one-time zero (covers all k-pads) ----
    for (int i = tid; i < OFF_B1S / 4; i += THREADS) ((uint32_t*)smem)[i] = 0u;
    __syncthreads();

    // ---- stage weights as tf32 ----
    for (int i = tid; i < 80 * 97; i += THREADS) {
        int n = i / 97, c = i - n * 97;
        B1w[n * AW1 + c] = f2tf(W1[i]);
    }
    for (int i = tid; i < 64 * 80; i += THREADS) {
        int n = i / 80, c = i - n * 80;
        B2w[n * AW2 + c] = f2tf(W2[i]);
    }
    if (tid < 80) b1s[tid] = b1[tid];
    if (tid < 64) b2s[tid] = b2[tid];
    __syncthreads();

    // warp tile: m32 x n40 (phase A) / m32 x n32 (phase B)
    const int mrow  = pg * 32;
    const int ncolA = ng * 40;
    const int ncolB = ng * 32;
    const int rA = (lane >> 2);           // frag row within m16
    const int cc = 2 * (lane & 3);        // acc col pair base within n8
    const int fc = (lane & 3);            // frag k col within k8

    // staging: pair p stages ONLY its own rows mrow..mrow+31.
    // pairtid 0..63 over warps {2p, 2p+1}; 2 threads per row.
    const int pairtid = (ng << 5) | lane;
    const int srow = mrow + (pairtid >> 1);
    const int sub  = pairtid & 1;

    const int ntiles = (E + TILE - 1) / TILE;

    // ---- prefetch first tile into registers ----
    float4 px[12];
    float  pef;
    {
        int tile0 = blockIdx.x;
        if (tile0 < ntiles) {
            size_t ge = (size_t)(tile0 * TILE + srow);
            bool ok = (int)(ge) < E;
            #pragma unroll
            for (int q = 0; q < 12; q++) {
                int k0 = (2 * q + sub) * 4;
                float4 x = make_float4(0.f, 0.f, 0.f, 0.f);
                if (ok) {
                    if      (k0 < 16) x = *(const float4*)(dstf + ge * 16 + k0);
                    else if (k0 < 48) x = *(const float4*)(dsth + ge * 32 + (k0 - 16));
                    else if (k0 < 64) x = *(const float4*)(srcf + ge * 16 + (k0 - 48));
                    else              x = *(const float4*)(srch + ge * 32 + (k0 - 64));
                }
                px[q] = x;
            }
            pef = (sub == 0 && ok) ? ef[ge] : 0.0f;
        }
    }

    for (int tile = blockIdx.x; tile < ntiles; tile += gridDim.x) {
        const int e0 = tile * TILE;

        // ---- STS prefetched rows -> A1 as tf32 (pair-local rows only) ----
        {
            uint32_t* rp = A1w + srow * AW1;
            #pragma unroll
            for (int q = 0; q < 12; q++) {
                int k0 = (2 * q + sub) * 4;
                uint4 t;
                t.x = f2tf(px[q].x); t.y = f2tf(px[q].y);
                t.z = f2tf(px[q].z); t.w = f2tf(px[q].w);
                *(uint4*)(rp + k0) = t;
            }
            if (sub == 0) rp[96] = f2tf(pef);   // cols 97..107 stay zero from init
        }
        PAIR_BAR(pg);   // bar1: pair's A1 rows visible; gates pair's mmaA

        // ---- prefetch NEXT tile (latency hidden behind mmaA/epiA/mmaB) ----
        {
            int nt = tile + gridDim.x;
            if (nt < ntiles) {
                size_t ge = (size_t)(nt * TILE + srow);
                bool ok = (int)(ge) < E;
                #pragma unroll
                for (int q = 0; q < 12; q++) {
                    int k0 = (2 * q + sub) * 4;
                    float4 x = make_float4(0.f, 0.f, 0.f, 0.f);
                    if (ok) {
                        if      (k0 < 16) x = *(const float4*)(dstf + ge * 16 + k0);
                        else if (k0 < 48) x = *(const float4*)(dsth + ge * 32 + (k0 - 16));
                        else if (k0 < 64) x = *(const float4*)(srcf + ge * 16 + (k0 - 48));
                        else              x = *(const float4*)(srch + ge * 32 + (k0 - 64));
                    }
                    px[q] = x;
                }
                pef = (sub == 0 && ok) ? ef[ge] : 0.0f;
            }
        }

        // ---- phase A: H rows mrow..mrow+31, warp m32 x n40, 13 tf32 k8-steps ----
        float acc[2][5][4];
        #pragma unroll
        for (int h = 0; h < 2; h++)
            #pragma unroll
            for (int j = 0; j < 5; j++)
                #pragma unroll
                for (int q = 0; q < 4; q++) acc[h][j][q] = 0.0f;

        {
            const uint32_t* aR0 = A1w + (mrow + rA) * AW1 + fc;        // rows rA, rA+8
            const uint32_t* aR1 = A1w + (mrow + 16 + rA) * AW1 + fc;   // rows +16, +24
            const uint32_t* bR  = B1w + fc;

            #pragma unroll
            for (int s = 0; s < 13; s++) {
                const int k = s * 8;
                uint32_t a0 = aR0[k],            a1 = aR0[8 * AW1 + k];
                uint32_t a2 = aR0[k + 4],        a3 = aR0[8 * AW1 + k + 4];
                uint32_t c0 = aR1[k],            c1 = aR1[8 * AW1 + k];
                uint32_t c2 = aR1[k + 4],        c3 = aR1[8 * AW1 + k + 4];
                #pragma unroll
                for (int j = 0; j < 5; j++) {
                    const uint32_t* bp = bR + (ncolA + 8 * j + rA) * AW1 + k;
                    uint32_t b0 = bp[0], b1v = bp[4];
                    mma_tf32(acc[0][j], a0, a1, a2, a3, b0, b1v);
                    mma_tf32(acc[1][j], c0, c1, c2, c3, b0, b1v);
                }
            }
        }

        // ---- epilogue A: relu(+b1) -> tf32 -> A2 (pair-local rows) ----
        #pragma unroll
        for (int h = 0; h < 2; h++) {
            #pragma unroll
            for (int j = 0; j < 5; j++) {
                const int c0 = ncolA + 8 * j + cc;
                const float bb0 = b1s[c0], bb1 = b1s[c0 + 1];
                uint32_t* rp0 = A2w + (mrow + 16 * h + rA) * AW2;
                uint32_t* rp1 = rp0 + 8 * AW2;
                uint2 v0, v1;
                v0.x = f2tf(fmaxf(acc[h][j][0] + bb0, 0.0f));
                v0.y = f2tf(fmaxf(acc[h][j][1] + bb1, 0.0f));
                v1.x = f2tf(fmaxf(acc[h][j][2] + bb0, 0.0f));
                v1.y = f2tf(fmaxf(acc[h][j][3] + bb1, 0.0f));
                *(uint2*)(rp0 + c0) = v0;
                *(uint2*)(rp1 + c0) = v1;
            }
        }
        PAIR_BAR(pg);   // bar2: pair's A2 rows complete; proves pair's mmaA A1-reads done

        // ---- phase B: O rows mrow..mrow+31, warp m32 x n32, 10 tf32 k8-steps ----
        float acc2[2][4][4];
        #pragma unroll
        for (int h = 0; h < 2; h++)
            #pragma unroll
            for (int j = 0; j < 4; j++)
                #pragma unroll
                for (int q = 0; q < 4; q++) acc2[h][j][q] = 0.0f;

        {
            const uint32_t* aR0 = A2w + (mrow + rA) * AW2 + fc;
            const uint32_t* aR1 = A2w + (mrow + 16 + rA) * AW2 + fc;
            const uint32_t* bR  = B2w + fc;

            #pragma unroll
            for (int s = 0; s < 10; s++) {
                const int k = s * 8;
                uint32_t a0 = aR0[k],            a1 = aR0[8 * AW2 + k];
                uint32_t a2 = aR0[k + 4],        a3 = aR0[8 * AW2 + k + 4];
                uint32_t c0 = aR1[k],            c1 = aR1[8 * AW2 + k];
                uint32_t c2 = aR1[k + 4],        c3 = aR1[8 * AW2 + k + 4];
                #pragma unroll
                for (int j = 0; j < 4; j++) {
                    const uint32_t* bp = bR + (ncolB + 8 * j + rA) * AW2 + k;
                    uint32_t b0 = bp[0], b1v = bp[4];
                    mma_tf32(acc2[0][j], a0, a1, a2, a3, b0, b1v);
                    mma_tf32(acc2[1][j], c0, c1, c2, c3, b0, b1v);
                }
            }
        }

        // ---- epilogue B: tanh(+b2) -> direct STG.64 ----
        #pragma unroll
        for (int h = 0; h < 2; h++) {
            const int gr0 = e0 + mrow + 16 * h + rA;
            const int gr1 = gr0 + 8;
            #pragma unroll
            for (int j = 0; j < 4; j++) {
                const int c0 = ncolB + 8 * j + cc;
                const float bb0 = b2s[c0], bb1 = b2s[c0 + 1];
                if (gr0 < E) {
                    float2 v = make_float2(fast_tanh(acc2[h][j][0] + bb0),
                                           fast_tanh(acc2[h][j][1] + bb1));
                    *(float2*)(out + (size_t)gr0 * 64 + c0) = v;
                }
                if (gr1 < E) {
                    float2 v = make_float2(fast_tanh(acc2[h][j][2] + bb0),
                                           fast_tanh(acc2[h][j][3] + bb1));
                    *(float2*)(out + (size_t)gr1 * 64 + c0) = v;
                }
            }
        }
        // next iteration's STS(t+1) into this pair's A1 rows is safe: pair bar2
        // proved both pair warps finished mmaA(t); mmaB reads only A2/B2. All
        // A1/A2 rows are pair-private; B1/B2 are read-only weights.
    }
}

extern "C" void kernel_launch(void* const* d_in, const int* in_sizes, int n_in,
                              void* d_out, int out_size) {
    const float* dstf = (const float*)d_in[0];
    const float* dsth = (const float*)d_in[1];
    const float* srcf = (const float*)d_in[2];
    const float* srch = (const float*)d_in[3];
    const float* ef   = (const float*)d_in[4];
    const float* W1   = (const float*)d_in[5];
    const float* b1   = (const float*)d_in[6];
    const float* W2   = (const float*)d_in[7];
    const float* b2   = (const float*)d_in[8];
    float* out = (float*)d_out;
    const int E = in_sizes[4];
    (void)n_in; (void)out_size;

    cudaFuncSetAttribute(edge_mlp_tf32,
                         cudaFuncAttributeMaxDynamicSharedMemorySize, SMEM_TOTAL);
    int sms = 148;
    cudaDeviceGetAttribute(&sms, cudaDevAttrMultiProcessorCount, 0);

    edge_mlp_tf32<<<sms, THREADS, SMEM_TOTAL>>>(
        dstf, dsth, srcf, srch, ef, W1, b1, W2, b2, out, E);
}

// round 17
// speedup vs baseline: 1.6016x; 1.0606x over previous
#include <cuda_runtime.h>
#include <cstdint>

#define THREADS 256
#define TILE    128

// fp32/tf32 tiles. Word strides % 8 == 4 -> conflict-free LDS/ldmatrix phases.
#define AW1 108   // A1/W1 row stride in words (432 B; cols 0..96 data, 97..107 zero)
#define AW2 84    // A2/W2 row stride in words (336 B; cols 0..79)

#define OFF_A1  0         // 128*432 = 55296
#define OFF_A2  55296     // 128*336 = 43008 -> 98304
#define OFF_B1  98304     // 80*432  = 34560 -> 132864
#define OFF_B2  132864    // 64*336  = 21504 -> 154368
#define OFF_B1S 154368    // 80 f32
#define OFF_B2S 154688    // 64 f32
#define SMEM_TOTAL 154944

// pair barrier: warps {2p, 2p+1} sync on id p+1; pair spans 2 SMSPs so each
// SMSP hosts warps of two different pairs -> independent streams per scheduler.
#define PAIR_BAR(p) asm volatile("bar.sync %0, 64;" :: "r"((p) + 1) : "memory")

__device__ __forceinline__ uint32_t f2tf(float f) {
    uint32_t r; asm("cvt.rna.tf32.f32 %0, %1;" : "=r"(r) : "f"(f)); return r;
}

__device__ __forceinline__ uint32_t smem_u32(const void* p) {
    uint32_t a;
    asm("{ .reg .u64 t; cvta.to.shared.u64 t, %1; cvt.u32.u64 %0, t; }" : "=r"(a) : "l"(p));
    return a;
}

__device__ __forceinline__ float fast_tanh(float x) {
    float e = __expf(2.0f * x);
    return 1.0f - __fdividef(2.0f, e + 1.0f);
}

// ldmatrix on tf32 data viewed as b16 pairs: x4 loads a 16-row x 8-tf32-col tile
// (A-frag a0..a3) or an n16 x k8 B pair (b0_j, b0_j+1, b1_j, b1_j+1).
__device__ __forceinline__ void ldsm4(uint32_t& r0, uint32_t& r1, uint32_t& r2, uint32_t& r3,
                                      uint32_t addr) {
    asm volatile("ldmatrix.sync.aligned.m8n8.x4.shared.b16 {%0,%1,%2,%3}, [%4];"
        : "=r"(r0), "=r"(r1), "=r"(r2), "=r"(r3) : "r"(addr));
}
__device__ __forceinline__ void ldsm2(uint32_t& r0, uint32_t& r1, uint32_t addr) {
    asm volatile("ldmatrix.sync.aligned.m8n8.x2.shared.b16 {%0,%1}, [%2];"
        : "=r"(r0), "=r"(r1) : "r"(addr));
}

__device__ __forceinline__ void mma_tf32(float* d, uint32_t a0, uint32_t a1,
                                         uint32_t a2, uint32_t a3,
                                         uint32_t b0, uint32_t b1) {
    asm volatile(
        "mma.sync.aligned.m16n8k8.row.col.f32.tf32.tf32.f32 "
        "{%0,%1,%2,%3}, {%4,%5,%6,%7}, {%8,%9}, {%0,%1,%2,%3};"
        : "+f"(d[0]), "+f"(d[1]), "+f"(d[2]), "+f"(d[3])
        : "r"(a0), "r"(a1), "r"(a2), "r"(a3), "r"(b0), "r"(b1));
}

extern __shared__ char smem[];

__global__ void __launch_bounds__(THREADS, 1)
edge_mlp_tf32(const float* __restrict__ dstf, const float* __restrict__ dsth,
              const float* __restrict__ srcf, const float* __restrict__ srch,
              const float* __restrict__ ef,
              const float* __restrict__ W1, const float* __restrict__ b1,
              const float* __restrict__ W2, const float* __restrict__ b2,
              float* __restrict__ out, int E)
{
    const uint32_t sbase = smem_u32(smem);
    const int tid  = threadIdx.x;
    const int lane = tid & 31;
    const int warp = tid >> 5;            // 0..7
    const int pg   = warp >> 1;           // row-group / pair id (spans 2 SMSPs)
    const int ng   = warp & 1;            // n-group within pair
    float* b1s = (float*)(smem + OFF_B1S);
    float* b2s = (float*)(smem + OFF_B2S);

    uint32_t* A1w = (uint32_t*)(smem + OFF_A1);
    uint32_t* A2w = (uint32_t*)(smem + OFF_A2);
    uint32_t* B1w = (uint32_t*)(smem + OFF_B1);
    uint32_t* B2w = (uint32_t*)(smem + OFF_B2);

    // ---- one-time zero (covers all k-pads) ----
    for (int i = tid; i < OFF_B1S / 4; i += THREADS) ((uint32_t*)smem)[i] = 0u;
    __syncthreads();

    // ---- stage weights as tf32 ----
    for (int i = tid; i < 80 * 97; i += THREADS) {
        int n = i / 97, c = i - n * 97;
        B1w[n * AW1 + c] = f2tf(W1[i]);
    }
    for (int i = tid; i < 64 * 80; i += THREADS) {
        int n = i / 80, c = i - n * 80;
        B2w[n * AW2 + c] = f2tf(W2[i]);
    }
    if (tid < 80) b1s[tid] = b1[tid];
    if (tid < 64) b2s[tid] = b2[tid];
    __syncthreads();

    // warp tile: m32 x n40 (phase A) / m32 x n32 (phase B)
    const int mrow  = pg * 32;
    const int ncolA = ng * 40;
    const int ncolB = ng * 32;
    const int rA = (lane >> 2);           // frag row within m16
    const int cc = 2 * (lane & 3);        // acc col pair base within n8

    // ldmatrix lane address components (byte offsets)
    const int l15 = lane & 15;
    const int hi16 = (lane >> 4) * 16;    // +16B for second 8-byte-col half (x4)
    const int l7  = lane & 7;
    const int hi8 = ((lane >> 3) & 1) * 16;  // x2 variant

    // staging: pair p stages ONLY its own rows mrow..mrow+31; 2 threads/row.
    const int pairtid = (ng << 5) | lane;
    const int srow = mrow + (pairtid >> 1);
    const int sub  = pairtid & 1;

    const int ntiles = (E + TILE - 1) / TILE;

    // ---- prefetch first tile into registers ----
    float4 px[12];
    float  pef;
    {
        int tile0 = blockIdx.x;
        if (tile0 < ntiles) {
            size_t ge = (size_t)(tile0 * TILE + srow);
            bool ok = (int)(ge) < E;
            #pragma unroll
            for (int q = 0; q < 12; q++) {
                int k0 = (2 * q + sub) * 4;
                float4 x = make_float4(0.f, 0.f, 0.f, 0.f);
                if (ok) {
                    if      (k0 < 16) x = *(const float4*)(dstf + ge * 16 + k0);
                    else if (k0 < 48) x = *(const float4*)(dsth + ge * 32 + (k0 - 16));
                    else if (k0 < 64) x = *(const float4*)(srcf + ge * 16 + (k0 - 48));
                    else              x = *(const float4*)(srch + ge * 32 + (k0 - 64));
                }
                px[q] = x;
            }
            pef = (sub == 0 && ok) ? ef[ge] : 0.0f;
        }
    }

    for (int tile = blockIdx.x; tile < ntiles; tile += gridDim.x) {
        const int e0 = tile * TILE;

        // ---- STS prefetched rows -> A1 as tf32 (pair-local rows only) ----
        {
            uint32_t* rp = A1w + srow * AW1;
            #pragma unroll
            for (int q = 0; q < 12; q++) {
                int k0 = (2 * q + sub) * 4;
                uint4 t;
                t.x = f2tf(px[q].x); t.y = f2tf(px[q].y);
                t.z = f2tf(px[q].z); t.w = f2tf(px[q].w);
                *(uint4*)(rp + k0) = t;
            }
            if (sub == 0) rp[96] = f2tf(pef);   // cols 97..107 stay zero from init
        }
        PAIR_BAR(pg);   // bar1: pair's A1 rows visible; gates pair's mmaA

        // ---- prefetch NEXT tile (latency hidden behind mmaA/epiA/mmaB) ----
        {
            int nt = tile + gridDim.x;
            if (nt < ntiles) {
                size_t ge = (size_t)(nt * TILE + srow);
                bool ok = (int)(ge) < E;
                #pragma unroll
                for (int q = 0; q < 12; q++) {
                    int k0 = (2 * q + sub) * 4;
                    float4 x = make_float4(0.f, 0.f, 0.f, 0.f);
                    if (ok) {
                        if      (k0 < 16) x = *(const float4*)(dstf + ge * 16 + k0);
                        else if (k0 < 48) x = *(const float4*)(dsth + ge * 32 + (k0 - 16));
                        else if (k0 < 64) x = *(const float4*)(srcf + ge * 16 + (k0 - 48));
                        else              x = *(const float4*)(srch + ge * 32 + (k0 - 64));
                    }
                    px[q] = x;
                }
                pef = (sub == 0 && ok) ? ef[ge] : 0.0f;
            }
        }

        // ---- phase A: H rows mrow..mrow+31, warp m32 x n40, 13 tf32 k8-steps ----
        float acc[2][5][4];
        #pragma unroll
        for (int h = 0; h < 2; h++)
            #pragma unroll
            for (int j = 0; j < 5; j++)
                #pragma unroll
                for (int q = 0; q < 4; q++) acc[h][j][q] = 0.0f;

        {
            // A: rows mrow+l15 (+16 for upper m-half), +16B for lanes>=16
            const uint32_t aAd0 = sbase + OFF_A1 + (uint32_t)(mrow + l15) * (AW1 * 4) + hi16;
            const uint32_t aAd1 = aAd0 + 16 * (AW1 * 4);
            // B x4 pairs: n-rows ncolA+16jp+l15 ; x2 tail: ncolA+32+l7
            const uint32_t bAd0 = sbase + OFF_B1 + (uint32_t)(ncolA + l15)      * (AW1 * 4) + hi16;
            const uint32_t bAd1 = sbase + OFF_B1 + (uint32_t)(ncolA + 16 + l15) * (AW1 * 4) + hi16;
            const uint32_t bAd2 = sbase + OFF_B1 + (uint32_t)(ncolA + 32 + l7)  * (AW1 * 4) + hi8;

            #pragma unroll
            for (int s = 0; s < 13; s++) {
                const int kb = s * 32;   // 8 tf32 cols = 32 bytes per step
                uint32_t a0, a1, a2, a3, c0, c1, c2, c3;
                uint32_t q0, q1, q2, q3;
                ldsm4(a0, a1, a2, a3, aAd0 + kb);
                ldsm4(c0, c1, c2, c3, aAd1 + kb);
                ldsm4(q0, q1, q2, q3, bAd0 + kb);   // q0=b0(j0) q1=b0(j1) q2=b1(j0) q3=b1(j1)
                mma_tf32(acc[0][0], a0, a1, a2, a3, q0, q2);
                mma_tf32(acc[1][0], c0, c1, c2, c3, q0, q2);
                mma_tf32(acc[0][1], a0, a1, a2, a3, q1, q3);
                mma_tf32(acc[1][1], c0, c1, c2, c3, q1, q3);
                ldsm4(q0, q1, q2, q3, bAd1 + kb);   // j2, j3
                mma_tf32(acc[0][2], a0, a1, a2, a3, q0, q2);
                mma_tf32(acc[1][2], c0, c1, c2, c3, q0, q2);
                mma_tf32(acc[0][3], a0, a1, a2, a3, q1, q3);
                mma_tf32(acc[1][3], c0, c1, c2, c3, q1, q3);
                ldsm2(q0, q1, bAd2 + kb);           // j4
                mma_tf32(acc[0][4], a0, a1, a2, a3, q0, q1);
                mma_tf32(acc[1][4], c0, c1, c2, c3, q0, q1);
            }
        }

        // ---- epilogue A: relu(+b1) -> tf32 -> A2 (pair-local rows) ----
        #pragma unroll
        for (int h = 0; h < 2; h++) {
            #pragma unroll
            for (int j = 0; j < 5; j++) {
                const int c0 = ncolA + 8 * j + cc;
                const float bb0 = b1s[c0], bb1 = b1s[c0 + 1];
                uint32_t* rp0 = A2w + (mrow + 16 * h + rA) * AW2;
                uint32_t* rp1 = rp0 + 8 * AW2;
                uint2 v0, v1;
                v0.x = f2tf(fmaxf(acc[h][j][0] + bb0, 0.0f));
                v0.y = f2tf(fmaxf(acc[h][j][1] + bb1, 0.0f));
                v1.x = f2tf(fmaxf(acc[h][j][2] + bb0, 0.0f));
                v1.y = f2tf(fmaxf(acc[h][j][3] + bb1, 0.0f));
                *(uint2*)(rp0 + c0) = v0;
                *(uint2*)(rp1 + c0) = v1;
            }
        }
        PAIR_BAR(pg);   // bar2: pair's A2 rows complete; proves pair's mmaA A1-reads done

        // ---- phase B: O rows mrow..mrow+31, warp m32 x n32, 10 tf32 k8-steps ----
        float acc2[2][4][4];
        #pragma unroll
        for (int h = 0; h < 2; h++)
            #pragma unroll
            for (int j = 0; j < 4; j++)
                #pragma unroll
                for (int q = 0; q < 4; q++) acc2[h][j][q] = 0.0f;

        {
            const uint32_t aAd0 = sbase + OFF_A2 + (uint32_t)(mrow + l15) * (AW2 * 4) + hi16;
            const uint32_t aAd1 = aAd0 + 16 * (AW2 * 4);
            const uint32_t bAd0 = sbase + OFF_B2 + (uint32_t)(ncolB + l15)      * (AW2 * 4) + hi16;
            const uint32_t bAd1 = sbase + OFF_B2 + (uint32_t)(ncolB + 16 + l15) * (AW2 * 4) + hi16;

            #pragma unroll
            for (int s = 0; s < 10; s++) {
                const int kb = s * 32;
                uint32_t a0, a1, a2, a3, c0, c1, c2, c3;
                uint32_t q0, q1, q2, q3;
                ldsm4(a0, a1, a2, a3, aAd0 + kb);
                ldsm4(c0, c1, c2, c3, aAd1 + kb);
                ldsm4(q0, q1, q2, q3, bAd0 + kb);
                mma_tf32(acc2[0][0], a0, a1, a2, a3, q0, q2);
                mma_tf32(acc2[1][0], c0, c1, c2, c3, q0, q2);
                mma_tf32(acc2[0][1], a0, a1, a2, a3, q1, q3);
                mma_tf32(acc2[1][1], c0, c1, c2, c3, q1, q3);
                ldsm4(q0, q1, q2, q3, bAd1 + kb);
                mma_tf32(acc2[0][2], a0, a1, a2, a3, q0, q2);
                mma_tf32(acc2[1][2], c0, c1, c2, c3, q0, q2);
                mma_tf32(acc2[0][3], a0, a1, a2, a3, q1, q3);
                mma_tf32(acc2[1][3], c0, c1, c2, c3, q1, q3);
            }
        }

        // ---- epilogue B: tanh(+b2) -> direct STG.64 ----
        #pragma unroll
        for (int h = 0; h < 2; h++) {
            const int gr0 = e0 + mrow + 16 * h + rA;
            const int gr1 = gr0 + 8;
            #pragma unroll
            for (int j = 0; j < 4; j++) {
                const int c0 = ncolB + 8 * j + cc;
                const float bb0 = b2s[c0], bb1 = b2s[c0 + 1];
                if (gr0 < E) {
                    float2 v = make_float2(fast_tanh(acc2[h][j][0] + bb0),
                                           fast_tanh(acc2[h][j][1] + bb1));
                    *(float2*)(out + (size_t)gr0 * 64 + c0) = v;
                }
                if (gr1 < E) {
                    float2 v = make_float2(fast_tanh(acc2[h][j][2] + bb0),
                                           fast_tanh(acc2[h][j][3] + bb1));
                    *(float2*)(out + (size_t)gr1 * 64 + c0) = v;
                }
            }
        }
        // next iteration's STS(t+1) into this pair's A1 rows is safe: pair bar2
        // proved both pair warps finished mmaA(t); mmaB reads only A2/B2. All
        // A1/A2 rows are pair-private; B1/B2 are read-only weights.
    }
}

extern "C" void kernel_launch(void* const* d_in, const int* in_sizes, int n_in,
                              void* d_out, int out_size) {
    const float* dstf = (const float*)d_in[0];
    const float* dsth = (const float*)d_in[1];
    const float* srcf = (const float*)d_in[2];
    const float* srch = (const float*)d_in[3];
    const float* ef   = (const float*)d_in[4];
    const float* W1   = (const float*)d_in[5];
    const float* b1   = (const float*)d_in[6];
    const float* W2   = (const float*)d_in[7];
    const float* b2   = (const float*)d_in[8];
    float* out = (float*)d_out;
    const int E = in_sizes[4];
    (void)n_in; (void)out_size;

    cudaFuncSetAttribute(edge_mlp_tf32,
                         cudaFuncAttributeMaxDynamicSharedMemorySize, SMEM_TOTAL);
    int sms = 148;
    cudaDeviceGetAttribute(&sms, cudaDevAttrMultiProcessorCount, 0);

    edge_mlp_tf32<<<sms, THREADS, SMEM_TOTAL>>>(
        dstf, dsth, srcf, srch, ef, W1, b1, W2, b2, out, E);
}